// round 3
// baseline (speedup 1.0000x reference)
#include <cuda_runtime.h>

#define NN   100000
#define NE   1600000
#define INF  128
#define HF   64
#define OUTF 32

// ---- scratch (static device globals; no allocation anywhere) ----
__device__ __align__(16) float g_deg [NN];
__device__ __align__(16) float g_dinv[NN];
__device__ __align__(16) float g_norm[NE];
__device__ __align__(16) int   g_row [NE];
__device__ __align__(16) int   g_col [NE];
__device__ __align__(16) float g_h1  [NN * HF];   // X @ W1
__device__ __align__(16) float g_agg1[NN * HF];   // aggregated layer-1 (pre bias/relu)
__device__ __align__(16) float g_h2  [NN * OUTF]; // relu(agg1+b1) @ W2
__device__ unsigned int g_flag;                   // 0 = int64 edge_index, 1 = int32

// ---------------------------------------------------------------
__global__ void k_init_deg() {
    int i = blockIdx.x * 256 + threadIdx.x;
    if (i < NN) g_deg[i] = 1.0f;   // self-loop weight
    if (i == 0) g_flag = 0u;
}

// Detect edge_index dtype: view as u32[2*NE]. int64 (values < 2^31, >=0)
// => all odd (high) words are zero. int32 => odd words are random indices.
__global__ void k_detect(const unsigned int* __restrict__ ei32) {
    int i = blockIdx.x * 256 + threadIdx.x;
    if (i < NE) {
        if (ei32[2 * i + 1] != 0u) atomicOr(&g_flag, 1u);
    }
}

__global__ void k_edge_deg(const int* __restrict__ ei32,
                           const float* __restrict__ ew) {
    int e = blockIdx.x * 256 + threadIdx.x;
    if (e >= NE) return;
    int r, c;
    if (g_flag) {               // int32 layout: [row[NE], col[NE]]
        r = ei32[e];
        c = ei32[NE + e];
    } else {                    // int64 layout: low words at even positions
        r = ei32[2 * e];
        c = ei32[2 * (NE + e)];
    }
    g_row[e] = r;
    g_col[e] = c;
    atomicAdd(&g_deg[c], ew[e]);
}

__global__ void k_dinv() {
    int i = blockIdx.x * 256 + threadIdx.x;
    if (i < NN) g_dinv[i] = rsqrtf(g_deg[i]);   // deg >= 1 always
}

__global__ void k_norm(const float* __restrict__ ew) {
    int e = blockIdx.x * 256 + threadIdx.x;
    if (e >= NE) return;
    g_norm[e] = g_dinv[g_row[e]] * ew[e] * g_dinv[g_col[e]];
}

// ---------------------------------------------------------------
// GEMM1: H1 = X[NN,128] @ W1[128,64]; agg1 = dinv^2 * H1 (self-loop term)
// tile: 128 nodes/block, 256 threads; thread = 4 nodes (ng + 32j) x 8 outputs
// dynamic smem: Xs[128][132] + Ws[128][64]
#define G1_SMEM ((128 * 132 + 128 * 64) * 4)

__global__ __launch_bounds__(256) void k_gemm1(const float* __restrict__ x,
                                               const float* __restrict__ W1) {
    extern __shared__ float sh[];
    float* Xs = sh;              // 128 x 132 (pad 4 -> conflict-free)
    float* Ws = sh + 128 * 132;  // 128 x 64

    int nb = blockIdx.x * 128;

    for (int i = threadIdx.x; i < 128 * 64 / 4; i += 256)
        ((float4*)Ws)[i] = ((const float4*)W1)[i];

    for (int i = threadIdx.x; i < 128 * 32; i += 256) {
        int node = i >> 5, k4 = i & 31;
        int gn = nb + node;
        float4 v = make_float4(0.f, 0.f, 0.f, 0.f);
        if (gn < NN) v = ((const float4*)x)[gn * 32 + k4];
        *(float4*)&Xs[node * 132 + k4 * 4] = v;
    }
    __syncthreads();

    int fg = threadIdx.x & 7;   // output group: f = fg*8 .. fg*8+7
    int ng = threadIdx.x >> 3;  // node: ng + 32*j

    float acc[4][8];
#pragma unroll
    for (int j = 0; j < 4; j++)
#pragma unroll
        for (int f = 0; f < 8; f++) acc[j][f] = 0.f;

#pragma unroll 4
    for (int k = 0; k < 128; k++) {
        float xv[4];
#pragma unroll
        for (int j = 0; j < 4; j++) xv[j] = Xs[(ng + 32 * j) * 132 + k];
        float4 wa = *(const float4*)&Ws[k * 64 + fg * 8];
        float4 wb = *(const float4*)&Ws[k * 64 + fg * 8 + 4];
#pragma unroll
        for (int j = 0; j < 4; j++) {
            acc[j][0] += xv[j] * wa.x; acc[j][1] += xv[j] * wa.y;
            acc[j][2] += xv[j] * wa.z; acc[j][3] += xv[j] * wa.w;
            acc[j][4] += xv[j] * wb.x; acc[j][5] += xv[j] * wb.y;
            acc[j][6] += xv[j] * wb.z; acc[j][7] += xv[j] * wb.w;
        }
    }

#pragma unroll
    for (int j = 0; j < 4; j++) {
        int gn = nb + ng + 32 * j;
        if (gn >= NN) continue;
        float di = g_dinv[gn];
        float d2 = di * di;
        float4 v0 = make_float4(acc[j][0], acc[j][1], acc[j][2], acc[j][3]);
        float4 v1 = make_float4(acc[j][4], acc[j][5], acc[j][6], acc[j][7]);
        ((float4*)g_h1)[gn * 16 + fg * 2]     = v0;
        ((float4*)g_h1)[gn * 16 + fg * 2 + 1] = v1;
        float4 a0 = make_float4(d2 * v0.x, d2 * v0.y, d2 * v0.z, d2 * v0.w);
        float4 a1 = make_float4(d2 * v1.x, d2 * v1.y, d2 * v1.z, d2 * v1.w);
        ((float4*)g_agg1)[gn * 16 + fg * 2]     = a0;
        ((float4*)g_agg1)[gn * 16 + fg * 2 + 1] = a1;
    }
}

// ---------------------------------------------------------------
// Scatter layer 1: 16 threads per edge, float4 chunk each, scalar REDs.
__global__ __launch_bounds__(256) void k_scatter1() {
    int t = blockIdx.x * 256 + threadIdx.x;   // up to 25.6M < 2^31
    int e = t >> 4, j = t & 15;
    if (e >= NE) return;
    int r = g_row[e], c = g_col[e];
    float nm = g_norm[e];
    float4 v = ((const float4*)g_h1)[r * 16 + j];
    float* dst = &g_agg1[c * 64 + j * 4];
    atomicAdd(dst + 0, nm * v.x);
    atomicAdd(dst + 1, nm * v.y);
    atomicAdd(dst + 2, nm * v.z);
    atomicAdd(dst + 3, nm * v.w);
}

// ---------------------------------------------------------------
// GEMM2: H2 = relu(agg1 + b1) @ W2[64,32]; out = b2 + dinv^2 * H2
// tile: 128 nodes/block, thread = 4 nodes x 4 outputs
__global__ __launch_bounds__(256) void k_gemm2(const float* __restrict__ W2,
                                               const float* __restrict__ b1,
                                               const float* __restrict__ b2,
                                               float* __restrict__ out) {
    __shared__ float Xs[128 * 68];  // 128 x (64+4)
    __shared__ float Ws[64 * 32];

    int nb = blockIdx.x * 128;

    for (int i = threadIdx.x; i < 64 * 32 / 4; i += 256)
        ((float4*)Ws)[i] = ((const float4*)W2)[i];

    for (int i = threadIdx.x; i < 128 * 16; i += 256) {
        int node = i >> 4, k4 = i & 15;
        int gn = nb + node;
        float4 v = make_float4(0.f, 0.f, 0.f, 0.f);
        if (gn < NN) {
            float4 a  = ((const float4*)g_agg1)[gn * 16 + k4];
            float4 bb = ((const float4*)b1)[k4];
            v.x = fmaxf(a.x + bb.x, 0.f);
            v.y = fmaxf(a.y + bb.y, 0.f);
            v.z = fmaxf(a.z + bb.z, 0.f);
            v.w = fmaxf(a.w + bb.w, 0.f);
        }
        *(float4*)&Xs[node * 68 + k4 * 4] = v;
    }
    __syncthreads();

    int fg = threadIdx.x & 7;   // f = fg*4 .. fg*4+3
    int ng = threadIdx.x >> 3;  // node: ng + 32*j

    float acc[4][4];
#pragma unroll
    for (int j = 0; j < 4; j++)
#pragma unroll
        for (int f = 0; f < 4; f++) acc[j][f] = 0.f;

#pragma unroll 4
    for (int k = 0; k < 64; k++) {
        float xv[4];
#pragma unroll
        for (int j = 0; j < 4; j++) xv[j] = Xs[(ng + 32 * j) * 68 + k];
        float4 w = *(const float4*)&Ws[k * 32 + fg * 4];
#pragma unroll
        for (int j = 0; j < 4; j++) {
            acc[j][0] += xv[j] * w.x; acc[j][1] += xv[j] * w.y;
            acc[j][2] += xv[j] * w.z; acc[j][3] += xv[j] * w.w;
        }
    }

#pragma unroll
    for (int j = 0; j < 4; j++) {
        int gn = nb + ng + 32 * j;
        if (gn >= NN) continue;
        float di = g_dinv[gn];
        float d2 = di * di;
        float4 v = make_float4(acc[j][0], acc[j][1], acc[j][2], acc[j][3]);
        ((float4*)g_h2)[gn * 8 + fg] = v;
        float4 bb = ((const float4*)b2)[fg];
        float4 o = make_float4(bb.x + d2 * v.x, bb.y + d2 * v.y,
                               bb.z + d2 * v.z, bb.w + d2 * v.w);
        ((float4*)out)[gn * 8 + fg] = o;  // initializes poisoned d_out
    }
}

// ---------------------------------------------------------------
// Scatter layer 2: 8 threads per edge, float4 chunk each -> d_out
__global__ __launch_bounds__(256) void k_scatter2(float* __restrict__ out) {
    int t = blockIdx.x * 256 + threadIdx.x;   // up to 12.8M
    int e = t >> 3, j = t & 7;
    if (e >= NE) return;
    int r = g_row[e], c = g_col[e];
    float nm = g_norm[e];
    float4 v = ((const float4*)g_h2)[r * 8 + j];
    float* dst = &out[c * 32 + j * 4];
    atomicAdd(dst + 0, nm * v.x);
    atomicAdd(dst + 1, nm * v.y);
    atomicAdd(dst + 2, nm * v.z);
    atomicAdd(dst + 3, nm * v.w);
}

// ---------------------------------------------------------------
static const void* by_size(void* const* d_in, const int* in_sizes, int n_in,
                           long long want) {
    for (int i = 0; i < n_in; i++)
        if ((long long)in_sizes[i] == want) return d_in[i];
    return 0;
}

extern "C" void kernel_launch(void* const* d_in, const int* in_sizes, int n_in,
                              void* d_out, int out_size) {
    // Match inputs by (distinct) element counts — immune to ordering surprises.
    const float* x   = (const float*)by_size(d_in, in_sizes, n_in, (long long)NN * INF);   // 12.8M
    const void*  ei  =               by_size(d_in, in_sizes, n_in, 2LL * NE);              // 3.2M
    const float* ew  = (const float*)by_size(d_in, in_sizes, n_in, (long long)NE);         // 1.6M
    const float* W1  = (const float*)by_size(d_in, in_sizes, n_in, (long long)INF * HF);   // 8192
    const float* b1  = (const float*)by_size(d_in, in_sizes, n_in, (long long)HF);         // 64
    const float* W2  = (const float*)by_size(d_in, in_sizes, n_in, (long long)HF * OUTF);  // 2048
    const float* b2  = (const float*)by_size(d_in, in_sizes, n_in, (long long)OUTF);       // 32
    float* out = (float*)d_out;

    // idempotent; not a stream op, safe under graph capture
    cudaFuncSetAttribute(k_gemm1, cudaFuncAttributeMaxDynamicSharedMemorySize, G1_SMEM);

    k_init_deg<<<(NN + 255) / 256, 256>>>();
    k_detect  <<<(NE + 255) / 256, 256>>>((const unsigned int*)ei);
    k_edge_deg<<<(NE + 255) / 256, 256>>>((const int*)ei, ew);
    k_dinv    <<<(NN + 255) / 256, 256>>>();
    k_norm    <<<(NE + 255) / 256, 256>>>(ew);

    k_gemm1<<<(NN + 127) / 128, 256, G1_SMEM>>>(x, W1);
    k_scatter1<<<(NE * 16 + 255) / 256, 256>>>();

    k_gemm2<<<(NN + 127) / 128, 256>>>(W2, b1, b2, out);
    k_scatter2<<<(NE * 8 + 255) / 256, 256>>>(out);
}

// round 4
// speedup vs baseline: 1.7388x; 1.7388x over previous
#include <cuda_runtime.h>

#define NN   100000
#define NE   1600000
#define INF  128
#define HF   64
#define OUTF 32

#define SCAN_B 1024
#define SCAN_G ((NN + SCAN_B - 1) / SCAN_B)   // 98

// ---- scratch (static device globals; no allocation anywhere) ----
__device__ __align__(16) float g_deg   [NN];
__device__ __align__(16) float g_dinv  [NN];
__device__ __align__(16) int   g_cnt   [NN];      // in-degree histogram (by col)
__device__ __align__(16) int   g_cursor[NN];      // CSR fill cursors
__device__ __align__(16) int   g_off   [NN + 1];  // CSR offsets (exclusive)
__device__ __align__(16) int   g_bsum  [SCAN_G];  // scan block sums
__device__ __align__(16) int   g_row   [NE];
__device__ __align__(16) int   g_col   [NE];
__device__ __align__(16) int   g_csr_row [NE];    // source node per CSR slot
__device__ __align__(16) float g_csr_norm[NE];    // norm per CSR slot
__device__ __align__(16) float g_h1 [NN * HF];    // X @ W1
__device__ __align__(16) float g_z1 [NN * HF];    // relu(agg1 + b1)
__device__ __align__(16) float g_h2 [NN * OUTF];  // z1 @ W2
__device__ unsigned int g_flag;                   // 0 = int64 edge_index, 1 = int32

// ---------------------------------------------------------------
__global__ void k_init() {
    int i = blockIdx.x * 256 + threadIdx.x;
    if (i < NN) {
        g_deg[i] = 1.0f;   // self-loop weight
        g_cnt[i] = 0;
        g_cursor[i] = 0;
    }
    if (i == 0) g_flag = 0u;
}

// Detect edge_index dtype: view as u32[2*NE]. int64 (values in [0,2^31))
// => all odd (high) words are zero. int32 => odd words are random indices.
__global__ void k_detect(const unsigned int* __restrict__ ei32) {
    int i = blockIdx.x * 256 + threadIdx.x;
    if (i < NE && ei32[2 * i + 1] != 0u) atomicOr(&g_flag, 1u);
}

__global__ void k_edge_deg(const int* __restrict__ ei32,
                           const float* __restrict__ ew) {
    int e = blockIdx.x * 256 + threadIdx.x;
    if (e >= NE) return;
    int r, c;
    if (g_flag) {               // int32 layout: [row[NE], col[NE]]
        r = ei32[e];
        c = ei32[NE + e];
    } else {                    // int64 layout: low words at even positions
        r = ei32[2 * e];
        c = ei32[2 * (NE + e)];
    }
    g_row[e] = r;
    g_col[e] = c;
    atomicAdd(&g_deg[c], ew[e]);
    atomicAdd(&g_cnt[c], 1);
}

__global__ void k_dinv() {
    int i = blockIdx.x * 256 + threadIdx.x;
    if (i < NN) g_dinv[i] = rsqrtf(g_deg[i]);   // deg >= 1 always
}

// ---- 3-kernel exclusive scan of g_cnt -> g_off -----------------
__global__ __launch_bounds__(SCAN_B) void k_scan1() {
    __shared__ int sh[SCAN_B];
    int t = threadIdx.x;
    int i = blockIdx.x * SCAN_B + t;
    int v = (i < NN) ? g_cnt[i] : 0;
    sh[t] = v;
    __syncthreads();
#pragma unroll
    for (int s = 1; s < SCAN_B; s <<= 1) {
        int a = (t >= s) ? sh[t - s] : 0;
        __syncthreads();
        sh[t] += a;
        __syncthreads();
    }
    if (i < NN) g_off[i] = sh[t] - v;           // exclusive within block
    if (t == SCAN_B - 1) g_bsum[blockIdx.x] = sh[t];
}

__global__ void k_scan2() {
    __shared__ int sh[SCAN_G];
    int t = threadIdx.x;
    if (t < SCAN_G) sh[t] = g_bsum[t];
    __syncthreads();
    if (t == 0) {
        int s = 0;
        for (int i = 0; i < SCAN_G; i++) { int v = sh[i]; sh[i] = s; s += v; }
        g_off[NN] = NE;
    }
    __syncthreads();
    if (t < SCAN_G) g_bsum[t] = sh[t];
}

__global__ __launch_bounds__(SCAN_B) void k_scan3() {
    int i = blockIdx.x * SCAN_B + threadIdx.x;
    if (i < NN && blockIdx.x > 0) g_off[i] += g_bsum[blockIdx.x];
}

// CSR fill with fused norm computation
__global__ void k_csr_fill(const float* __restrict__ ew) {
    int e = blockIdx.x * 256 + threadIdx.x;
    if (e >= NE) return;
    int r = g_row[e], c = g_col[e];
    int pos = g_off[c] + atomicAdd(&g_cursor[c], 1);
    g_csr_row[pos]  = r;
    g_csr_norm[pos] = g_dinv[r] * ew[e] * g_dinv[c];
}

// ---------------------------------------------------------------
// GEMM1: H1 = X[NN,128] @ W1[128,64]
#define G1_SMEM ((128 * 132 + 128 * 64) * 4)

__global__ __launch_bounds__(256) void k_gemm1(const float* __restrict__ x,
                                               const float* __restrict__ W1) {
    extern __shared__ float sh[];
    float* Xs = sh;              // 128 x 132 (pad 4 -> conflict-free)
    float* Ws = sh + 128 * 132;  // 128 x 64

    int nb = blockIdx.x * 128;

    for (int i = threadIdx.x; i < 128 * 64 / 4; i += 256)
        ((float4*)Ws)[i] = ((const float4*)W1)[i];

    for (int i = threadIdx.x; i < 128 * 32; i += 256) {
        int node = i >> 5, k4 = i & 31;
        int gn = nb + node;
        float4 v = make_float4(0.f, 0.f, 0.f, 0.f);
        if (gn < NN) v = ((const float4*)x)[gn * 32 + k4];
        *(float4*)&Xs[node * 132 + k4 * 4] = v;
    }
    __syncthreads();

    int fg = threadIdx.x & 7;   // output group: f = fg*8 .. fg*8+7
    int ng = threadIdx.x >> 3;  // node: ng + 32*j

    float acc[4][8];
#pragma unroll
    for (int j = 0; j < 4; j++)
#pragma unroll
        for (int f = 0; f < 8; f++) acc[j][f] = 0.f;

#pragma unroll 4
    for (int k = 0; k < 128; k++) {
        float xv[4];
#pragma unroll
        for (int j = 0; j < 4; j++) xv[j] = Xs[(ng + 32 * j) * 132 + k];
        float4 wa = *(const float4*)&Ws[k * 64 + fg * 8];
        float4 wb = *(const float4*)&Ws[k * 64 + fg * 8 + 4];
#pragma unroll
        for (int j = 0; j < 4; j++) {
            acc[j][0] += xv[j] * wa.x; acc[j][1] += xv[j] * wa.y;
            acc[j][2] += xv[j] * wa.z; acc[j][3] += xv[j] * wa.w;
            acc[j][4] += xv[j] * wb.x; acc[j][5] += xv[j] * wb.y;
            acc[j][6] += xv[j] * wb.z; acc[j][7] += xv[j] * wb.w;
        }
    }

#pragma unroll
    for (int j = 0; j < 4; j++) {
        int gn = nb + ng + 32 * j;
        if (gn >= NN) continue;
        ((float4*)g_h1)[gn * 16 + fg * 2] =
            make_float4(acc[j][0], acc[j][1], acc[j][2], acc[j][3]);
        ((float4*)g_h1)[gn * 16 + fg * 2 + 1] =
            make_float4(acc[j][4], acc[j][5], acc[j][6], acc[j][7]);
    }
}

// ---------------------------------------------------------------
// Gather layer 1: one warp per node. lane covers features [2*lane, 2*lane+1].
// z1 = relu(b1 + dinv^2*H1[c] + sum_e norm_e * H1[row_e])
__global__ __launch_bounds__(256) void k_gather1(const float* __restrict__ b1) {
    int warp = (blockIdx.x * 256 + threadIdx.x) >> 5;
    int lane = threadIdx.x & 31;
    if (warp >= NN) return;
    int c = warp;

    const float2* H = (const float2*)g_h1;
    float di = g_dinv[c];
    float d2 = di * di;
    float2 hc = H[c * 32 + lane];
    float ax = d2 * hc.x, ay = d2 * hc.y;

    int beg = g_off[c], end = g_off[c + 1];
    int i = beg;
    for (; i + 1 < end; i += 2) {
        int   r0 = g_csr_row[i],     r1 = g_csr_row[i + 1];
        float n0 = g_csr_norm[i],    n1 = g_csr_norm[i + 1];
        float2 h0 = H[r0 * 32 + lane];
        float2 h1 = H[r1 * 32 + lane];
        ax += n0 * h0.x + n1 * h1.x;
        ay += n0 * h0.y + n1 * h1.y;
    }
    if (i < end) {
        int   r0 = g_csr_row[i];
        float n0 = g_csr_norm[i];
        float2 h0 = H[r0 * 32 + lane];
        ax += n0 * h0.x;
        ay += n0 * h0.y;
    }

    float2 bb = ((const float2*)b1)[lane];
    float2 z;
    z.x = fmaxf(ax + bb.x, 0.f);
    z.y = fmaxf(ay + bb.y, 0.f);
    ((float2*)g_z1)[c * 32 + lane] = z;
}

// ---------------------------------------------------------------
// GEMM2: H2 = z1[NN,64] @ W2[64,32]
__global__ __launch_bounds__(256) void k_gemm2(const float* __restrict__ W2) {
    __shared__ float Xs[128 * 68];  // 128 x (64+4)
    __shared__ float Ws[64 * 32];

    int nb = blockIdx.x * 128;

    for (int i = threadIdx.x; i < 64 * 32 / 4; i += 256)
        ((float4*)Ws)[i] = ((const float4*)W2)[i];

    for (int i = threadIdx.x; i < 128 * 16; i += 256) {
        int node = i >> 4, k4 = i & 15;
        int gn = nb + node;
        float4 v = make_float4(0.f, 0.f, 0.f, 0.f);
        if (gn < NN) v = ((const float4*)g_z1)[gn * 16 + k4];
        *(float4*)&Xs[node * 68 + k4 * 4] = v;
    }
    __syncthreads();

    int fg = threadIdx.x & 7;   // f = fg*4 .. fg*4+3
    int ng = threadIdx.x >> 3;  // node: ng + 32*j

    float acc[4][4];
#pragma unroll
    for (int j = 0; j < 4; j++)
#pragma unroll
        for (int f = 0; f < 4; f++) acc[j][f] = 0.f;

#pragma unroll 4
    for (int k = 0; k < 64; k++) {
        float xv[4];
#pragma unroll
        for (int j = 0; j < 4; j++) xv[j] = Xs[(ng + 32 * j) * 68 + k];
        float4 w = *(const float4*)&Ws[k * 32 + fg * 4];
#pragma unroll
        for (int j = 0; j < 4; j++) {
            acc[j][0] += xv[j] * w.x; acc[j][1] += xv[j] * w.y;
            acc[j][2] += xv[j] * w.z; acc[j][3] += xv[j] * w.w;
        }
    }

#pragma unroll
    for (int j = 0; j < 4; j++) {
        int gn = nb + ng + 32 * j;
        if (gn >= NN) continue;
        ((float4*)g_h2)[gn * 8 + fg] =
            make_float4(acc[j][0], acc[j][1], acc[j][2], acc[j][3]);
    }
}

// ---------------------------------------------------------------
// Gather layer 2: one warp per node. lane = feature.
// out = b2 + dinv^2*H2[c] + sum_e norm_e * H2[row_e]
__global__ __launch_bounds__(256) void k_gather2(const float* __restrict__ b2,
                                                 float* __restrict__ out) {
    int warp = (blockIdx.x * 256 + threadIdx.x) >> 5;
    int lane = threadIdx.x & 31;
    if (warp >= NN) return;
    int c = warp;

    float di = g_dinv[c];
    float d2 = di * di;
    float acc = d2 * g_h2[c * 32 + lane];

    int beg = g_off[c], end = g_off[c + 1];
    int i = beg;
    for (; i + 1 < end; i += 2) {
        int   r0 = g_csr_row[i],  r1 = g_csr_row[i + 1];
        float n0 = g_csr_norm[i], n1 = g_csr_norm[i + 1];
        acc += n0 * g_h2[r0 * 32 + lane] + n1 * g_h2[r1 * 32 + lane];
    }
    if (i < end) {
        acc += g_csr_norm[i] * g_h2[g_csr_row[i] * 32 + lane];
    }

    out[c * 32 + lane] = acc + b2[lane];
}

// ---------------------------------------------------------------
static const void* by_size(void* const* d_in, const int* in_sizes, int n_in,
                           long long want) {
    for (int i = 0; i < n_in; i++)
        if ((long long)in_sizes[i] == want) return d_in[i];
    return 0;
}

extern "C" void kernel_launch(void* const* d_in, const int* in_sizes, int n_in,
                              void* d_out, int out_size) {
    // Match inputs by (distinct) element counts — immune to ordering surprises.
    const float* x  = (const float*)by_size(d_in, in_sizes, n_in, (long long)NN * INF);   // 12.8M
    const void*  ei =               by_size(d_in, in_sizes, n_in, 2LL * NE);              // 3.2M
    const float* ew = (const float*)by_size(d_in, in_sizes, n_in, (long long)NE);         // 1.6M
    const float* W1 = (const float*)by_size(d_in, in_sizes, n_in, (long long)INF * HF);   // 8192
    const float* b1 = (const float*)by_size(d_in, in_sizes, n_in, (long long)HF);         // 64
    const float* W2 = (const float*)by_size(d_in, in_sizes, n_in, (long long)HF * OUTF);  // 2048
    const float* b2 = (const float*)by_size(d_in, in_sizes, n_in, (long long)OUTF);       // 32
    float* out = (float*)d_out;

    cudaFuncSetAttribute(k_gemm1, cudaFuncAttributeMaxDynamicSharedMemorySize, G1_SMEM);

    k_init    <<<(NN + 255) / 256, 256>>>();
    k_detect  <<<(NE + 255) / 256, 256>>>((const unsigned int*)ei);
    k_edge_deg<<<(NE + 255) / 256, 256>>>((const int*)ei, ew);
    k_dinv    <<<(NN + 255) / 256, 256>>>();

    k_scan1<<<SCAN_G, SCAN_B>>>();
    k_scan2<<<1, SCAN_G>>>();
    k_scan3<<<SCAN_G, SCAN_B>>>();
    k_csr_fill<<<(NE + 255) / 256, 256>>>(ew);

    k_gemm1  <<<(NN + 127) / 128, 256, G1_SMEM>>>(x, W1);
    k_gather1<<<(NN * 32 + 255) / 256, 256>>>(b1);

    k_gemm2  <<<(NN + 127) / 128, 256>>>(W2);
    k_gather2<<<(NN * 32 + 255) / 256, 256>>>(b2, out);
}

// round 5
// speedup vs baseline: 1.8500x; 1.0640x over previous
#include <cuda_runtime.h>

#define NN   100000
#define NE   1600000
#define INF  128
#define HF   64
#define OUTF 32

#define SCAN_B 1024
#define SCAN_G ((NN + SCAN_B - 1) / SCAN_B)   // 98

// ---- scratch (static device globals; no allocation anywhere) ----
__device__ __align__(16) float g_deg   [NN];
__device__ __align__(16) float g_dinv  [NN];
__device__ __align__(16) int   g_cnt   [NN];      // in-degree histogram (by col)
__device__ __align__(16) int   g_cursor[NN];      // CSR fill cursors
__device__ __align__(16) int   g_off   [NN + 1];  // CSR offsets (exclusive)
__device__ __align__(16) int   g_bsum  [SCAN_G];  // scan block sums
__device__ __align__(16) int   g_rdy   [SCAN_G];  // scan ready flags
__device__ __align__(16) int   g_row   [NE];
__device__ __align__(16) int   g_col   [NE];
__device__ __align__(16) int2  g_csr   [NE];      // packed (src_row, norm-bits)
__device__ __align__(16) float g_h1 [NN * HF];    // X @ W1
__device__ __align__(16) float g_z1 [NN * HF];    // relu(agg1 + b1)
__device__ __align__(16) float g_h2 [NN * OUTF];  // z1 @ W2
__device__ unsigned int g_flag;                   // 0 = int64 edge_index, 1 = int32

// ---------------------------------------------------------------
// GEMM1: H1 = X[NN,128] @ W1[128,64] — with per-call init fused in.
#define G1_SMEM ((128 * 132 + 128 * 64) * 4)

__global__ __launch_bounds__(256) void k_gemm1(const float* __restrict__ x,
                                               const float* __restrict__ W1) {
    extern __shared__ float sh[];
    float* Xs = sh;              // 128 x 132 (pad 4 -> conflict-free)
    float* Ws = sh + 128 * 132;  // 128 x 64

    int nb = blockIdx.x * 128;

    // --- fused init: this block's 128 nodes + (block 0) scalars/flags ---
    if (threadIdx.x < 128) {
        int n0 = nb + threadIdx.x;
        if (n0 < NN) {
            g_deg[n0] = 1.0f;    // self-loop weight
            g_cnt[n0] = 0;
            g_cursor[n0] = 0;
        }
    }
    if (blockIdx.x == 0) {
        if (threadIdx.x == 0) g_flag = 0u;
        if (threadIdx.x < SCAN_G) g_rdy[threadIdx.x] = 0;
    }

    for (int i = threadIdx.x; i < 128 * 64 / 4; i += 256)
        ((float4*)Ws)[i] = ((const float4*)W1)[i];

    for (int i = threadIdx.x; i < 128 * 32; i += 256) {
        int node = i >> 5, k4 = i & 31;
        int gn = nb + node;
        float4 v = make_float4(0.f, 0.f, 0.f, 0.f);
        if (gn < NN) v = ((const float4*)x)[gn * 32 + k4];
        *(float4*)&Xs[node * 132 + k4 * 4] = v;
    }
    __syncthreads();

    int fg = threadIdx.x & 7;   // output group: f = fg*8 .. fg*8+7
    int ng = threadIdx.x >> 3;  // node: ng + 32*j

    float acc[4][8];
#pragma unroll
    for (int j = 0; j < 4; j++)
#pragma unroll
        for (int f = 0; f < 8; f++) acc[j][f] = 0.f;

#pragma unroll 4
    for (int k = 0; k < 128; k++) {
        float xv[4];
#pragma unroll
        for (int j = 0; j < 4; j++) xv[j] = Xs[(ng + 32 * j) * 132 + k];
        float4 wa = *(const float4*)&Ws[k * 64 + fg * 8];
        float4 wb = *(const float4*)&Ws[k * 64 + fg * 8 + 4];
#pragma unroll
        for (int j = 0; j < 4; j++) {
            acc[j][0] += xv[j] * wa.x; acc[j][1] += xv[j] * wa.y;
            acc[j][2] += xv[j] * wa.z; acc[j][3] += xv[j] * wa.w;
            acc[j][4] += xv[j] * wb.x; acc[j][5] += xv[j] * wb.y;
            acc[j][6] += xv[j] * wb.z; acc[j][7] += xv[j] * wb.w;
        }
    }

#pragma unroll
    for (int j = 0; j < 4; j++) {
        int gn = nb + ng + 32 * j;
        if (gn >= NN) continue;
        ((float4*)g_h1)[gn * 16 + fg * 2] =
            make_float4(acc[j][0], acc[j][1], acc[j][2], acc[j][3]);
        ((float4*)g_h1)[gn * 16 + fg * 2 + 1] =
            make_float4(acc[j][4], acc[j][5], acc[j][6], acc[j][7]);
    }
}

// ---------------------------------------------------------------
// Detect edge_index dtype: view as u32[2*NE]. int64 (values in [0,2^31))
// => all odd (high) words are zero. int32 => odd words are random indices.
__global__ void k_detect(const unsigned int* __restrict__ ei32) {
    int i = blockIdx.x * 256 + threadIdx.x;
    if (i < NE && ei32[2 * i + 1] != 0u) atomicOr(&g_flag, 1u);
}

__global__ void k_edge_deg(const int* __restrict__ ei32,
                           const float* __restrict__ ew) {
    int e = blockIdx.x * 256 + threadIdx.x;
    if (e >= NE) return;
    int r, c;
    if (g_flag) {               // int32 layout: [row[NE], col[NE]]
        r = ei32[e];
        c = ei32[NE + e];
    } else {                    // int64 layout: low words at even positions
        r = ei32[2 * e];
        c = ei32[2 * (NE + e)];
    }
    g_row[e] = r;
    g_col[e] = c;
    atomicAdd(&g_deg[c], ew[e]);
    atomicAdd(&g_cnt[c], 1);
}

// ---------------------------------------------------------------
// Single-pass exclusive scan of g_cnt -> g_off, fused with dinv.
// 98 blocks x 1024 threads; all blocks resident in wave 1 (148 SMs) so the
// release/acquire lookback spin cannot deadlock. Deterministic output.
__global__ __launch_bounds__(SCAN_B) void k_scan() {
    int t = threadIdx.x, b = blockIdx.x;
    int lane = t & 31, wid = t >> 5;
    int i = b * SCAN_B + t;

    // fused: dinv (g_deg final after k_edge_deg)
    if (i < NN) g_dinv[i] = rsqrtf(g_deg[i]);   // deg >= 1 always

    int v = (i < NN) ? g_cnt[i] : 0;

    // warp inclusive scan
    int val = v;
#pragma unroll
    for (int s = 1; s < 32; s <<= 1) {
        int u = __shfl_up_sync(0xffffffffu, val, s);
        if (lane >= s) val += u;
    }
    __shared__ int wsum[32];
    if (lane == 31) wsum[wid] = val;
    __syncthreads();
    if (wid == 0) {
        int w = wsum[lane];
#pragma unroll
        for (int s = 1; s < 32; s <<= 1) {
            int u = __shfl_up_sync(0xffffffffu, w, s);
            if (lane >= s) w += u;
        }
        wsum[lane] = w;
    }
    __syncthreads();
    int blk_excl = ((wid > 0) ? wsum[wid - 1] : 0) + val - v;
    int blk_total = wsum[31];

    // release this block's total
    if (t == 0) {
        g_bsum[b] = blk_total;
        __threadfence();
        atomicExch(&g_rdy[b], 1);
    }

    // lookback: prefix = sum of totals of blocks < b
    int p = 0;
    if (t < b) {   // b <= 97 < 1024
        while (atomicAdd(&g_rdy[t], 0) == 0) {}
        p = ((const volatile int*)g_bsum)[t];
    }
#pragma unroll
    for (int s = 16; s > 0; s >>= 1) p += __shfl_down_sync(0xffffffffu, p, s);
    __shared__ int psum[32];
    if (lane == 0) psum[wid] = p;
    __syncthreads();
    if (t == 0) {
        int s = 0;
#pragma unroll
        for (int w = 0; w < 32; w++) s += psum[w];
        psum[0] = s;
    }
    __syncthreads();
    int prefix = psum[0];

    if (i < NN) {
        g_off[i] = prefix + blk_excl;
        if (i == NN - 1) g_off[NN] = prefix + blk_excl + v;   // == NE
    }
}

// CSR fill with fused norm computation; packed (row, norm) int2.
__global__ void k_csr_fill(const float* __restrict__ ew) {
    int e = blockIdx.x * 256 + threadIdx.x;
    if (e >= NE) return;
    int r = g_row[e], c = g_col[e];
    int pos = g_off[c] + atomicAdd(&g_cursor[c], 1);
    float nm = g_dinv[r] * ew[e] * g_dinv[c];
    g_csr[pos] = make_int2(r, __float_as_int(nm));
}

// ---------------------------------------------------------------
// Gather layer 1: one warp per node. lane covers features [2*lane, 2*lane+1].
// z1 = relu(b1 + dinv^2*H1[c] + sum_e norm_e * H1[row_e]).  Unroll x4.
__global__ __launch_bounds__(256) void k_gather1(const float* __restrict__ b1) {
    int c = (blockIdx.x * 256 + threadIdx.x) >> 5;
    int lane = threadIdx.x & 31;
    if (c >= NN) return;

    const float2* H = (const float2*)g_h1;
    float di = g_dinv[c];
    float d2 = di * di;
    float2 hc = H[c * 32 + lane];
    float ax = d2 * hc.x, ay = d2 * hc.y;

    int beg = g_off[c], end = g_off[c + 1];
    int i = beg;
    for (; i + 3 < end; i += 4) {
        int2 e0 = g_csr[i],     e1 = g_csr[i + 1];
        int2 e2 = g_csr[i + 2], e3 = g_csr[i + 3];
        float2 h0 = H[e0.x * 32 + lane];
        float2 h1 = H[e1.x * 32 + lane];
        float2 h2 = H[e2.x * 32 + lane];
        float2 h3 = H[e3.x * 32 + lane];
        float n0 = __int_as_float(e0.y), n1 = __int_as_float(e1.y);
        float n2 = __int_as_float(e2.y), n3 = __int_as_float(e3.y);
        ax += n0 * h0.x + n1 * h1.x + n2 * h2.x + n3 * h3.x;
        ay += n0 * h0.y + n1 * h1.y + n2 * h2.y + n3 * h3.y;
    }
    for (; i < end; i++) {
        int2 e0 = g_csr[i];
        float2 h0 = H[e0.x * 32 + lane];
        float n0 = __int_as_float(e0.y);
        ax += n0 * h0.x;
        ay += n0 * h0.y;
    }

    float2 bb = ((const float2*)b1)[lane];
    float2 z;
    z.x = fmaxf(ax + bb.x, 0.f);
    z.y = fmaxf(ay + bb.y, 0.f);
    ((float2*)g_z1)[c * 32 + lane] = z;
}

// ---------------------------------------------------------------
// GEMM2: H2 = z1[NN,64] @ W2[64,32]
__global__ __launch_bounds__(256) void k_gemm2(const float* __restrict__ W2) {
    __shared__ float Xs[128 * 68];  // 128 x (64+4)
    __shared__ float Ws[64 * 32];

    int nb = blockIdx.x * 128;

    for (int i = threadIdx.x; i < 64 * 32 / 4; i += 256)
        ((float4*)Ws)[i] = ((const float4*)W2)[i];

    for (int i = threadIdx.x; i < 128 * 16; i += 256) {
        int node = i >> 4, k4 = i & 15;
        int gn = nb + node;
        float4 v = make_float4(0.f, 0.f, 0.f, 0.f);
        if (gn < NN) v = ((const float4*)g_z1)[gn * 16 + k4];
        *(float4*)&Xs[node * 68 + k4 * 4] = v;
    }
    __syncthreads();

    int fg = threadIdx.x & 7;   // f = fg*4 .. fg*4+3
    int ng = threadIdx.x >> 3;  // node: ng + 32*j

    float acc[4][4];
#pragma unroll
    for (int j = 0; j < 4; j++)
#pragma unroll
        for (int f = 0; f < 4; f++) acc[j][f] = 0.f;

#pragma unroll 4
    for (int k = 0; k < 64; k++) {
        float xv[4];
#pragma unroll
        for (int j = 0; j < 4; j++) xv[j] = Xs[(ng + 32 * j) * 68 + k];
        float4 w = *(const float4*)&Ws[k * 32 + fg * 4];
#pragma unroll
        for (int j = 0; j < 4; j++) {
            acc[j][0] += xv[j] * w.x; acc[j][1] += xv[j] * w.y;
            acc[j][2] += xv[j] * w.z; acc[j][3] += xv[j] * w.w;
        }
    }

#pragma unroll
    for (int j = 0; j < 4; j++) {
        int gn = nb + ng + 32 * j;
        if (gn >= NN) continue;
        ((float4*)g_h2)[gn * 8 + fg] =
            make_float4(acc[j][0], acc[j][1], acc[j][2], acc[j][3]);
    }
}

// ---------------------------------------------------------------
// Gather layer 2: one warp per node, lane = feature. Unroll x4.
// out = b2 + dinv^2*H2[c] + sum_e norm_e * H2[row_e]
__global__ __launch_bounds__(256) void k_gather2(const float* __restrict__ b2,
                                                 float* __restrict__ out) {
    int c = (blockIdx.x * 256 + threadIdx.x) >> 5;
    int lane = threadIdx.x & 31;
    if (c >= NN) return;

    float di = g_dinv[c];
    float d2 = di * di;
    float acc = d2 * g_h2[c * 32 + lane];

    int beg = g_off[c], end = g_off[c + 1];
    int i = beg;
    for (; i + 3 < end; i += 4) {
        int2 e0 = g_csr[i],     e1 = g_csr[i + 1];
        int2 e2 = g_csr[i + 2], e3 = g_csr[i + 3];
        float h0 = g_h2[e0.x * 32 + lane];
        float h1 = g_h2[e1.x * 32 + lane];
        float h2 = g_h2[e2.x * 32 + lane];
        float h3 = g_h2[e3.x * 32 + lane];
        acc += __int_as_float(e0.y) * h0 + __int_as_float(e1.y) * h1
             + __int_as_float(e2.y) * h2 + __int_as_float(e3.y) * h3;
    }
    for (; i < end; i++) {
        int2 e0 = g_csr[i];
        acc += __int_as_float(e0.y) * g_h2[e0.x * 32 + lane];
    }

    out[c * 32 + lane] = acc + b2[lane];
}

// ---------------------------------------------------------------
static const void* by_size(void* const* d_in, const int* in_sizes, int n_in,
                           long long want) {
    for (int i = 0; i < n_in; i++)
        if ((long long)in_sizes[i] == want) return d_in[i];
    return 0;
}

extern "C" void kernel_launch(void* const* d_in, const int* in_sizes, int n_in,
                              void* d_out, int out_size) {
    // Match inputs by (distinct) element counts — immune to ordering surprises.
    const float* x  = (const float*)by_size(d_in, in_sizes, n_in, (long long)NN * INF);   // 12.8M
    const void*  ei =               by_size(d_in, in_sizes, n_in, 2LL * NE);              // 3.2M
    const float* ew = (const float*)by_size(d_in, in_sizes, n_in, (long long)NE);         // 1.6M
    const float* W1 = (const float*)by_size(d_in, in_sizes, n_in, (long long)INF * HF);   // 8192
    const float* b1 = (const float*)by_size(d_in, in_sizes, n_in, (long long)HF);         // 64
    const float* W2 = (const float*)by_size(d_in, in_sizes, n_in, (long long)HF * OUTF);  // 2048
    const float* b2 = (const float*)by_size(d_in, in_sizes, n_in, (long long)OUTF);       // 32
    float* out = (float*)d_out;

    cudaFuncSetAttribute(k_gemm1, cudaFuncAttributeMaxDynamicSharedMemorySize, G1_SMEM);

    // Launch order puts k_gather1 in profiler slot 6 (-s 5 -c 1).
    k_gemm1   <<<(NN + 127) / 128, 256, G1_SMEM>>>(x, W1);   // 1 (+init)
    k_detect  <<<(NE + 255) / 256, 256>>>((const unsigned int*)ei); // 2
    k_edge_deg<<<(NE + 255) / 256, 256>>>((const int*)ei, ew);      // 3
    k_scan    <<<SCAN_G, SCAN_B>>>();                               // 4 (+dinv)
    k_csr_fill<<<(NE + 255) / 256, 256>>>(ew);                      // 5
    k_gather1 <<<(NN * 32 + 255) / 256, 256>>>(b1);                 // 6 <- profiled
    k_gemm2   <<<(NN + 127) / 128, 256>>>(W2);                      // 7
    k_gather2 <<<(NN * 32 + 255) / 256, 256>>>(b2, out);            // 8
}

// round 6
// speedup vs baseline: 2.0042x; 1.0833x over previous
#include <cuda_runtime.h>

#define NN   100000
#define NE   1600000
#define INF  128
#define HF   64
#define OUTF 32

#define PREP_B   256
#define PREP_G   592                      // 4 per SM on 148 SMs: all co-resident
#define NPB      ((NN + PREP_G - 1) / PREP_G)   // 169 nodes per block

// ---- scratch (static device globals; no allocation anywhere) ----
__device__ __align__(16) float g_deg   [NN];
__device__ __align__(16) float g_dinv  [NN];
__device__ __align__(16) int   g_cnt   [NN];      // in-degree histogram (by col)
__device__ __align__(16) int   g_cursor[NN];      // CSR fill cursors
__device__ __align__(16) int   g_off   [NN + 1];  // CSR offsets (exclusive)
__device__ __align__(16) int   g_bsum  [PREP_G];  // per-block count totals
__device__ __align__(16) int   g_row   [NE];
__device__ __align__(16) int   g_col   [NE];
__device__ __align__(16) int2  g_csr   [NE];      // packed (src_row, norm-bits)
__device__ __align__(16) float g_h1 [NN * HF];    // X @ W1
__device__ __align__(16) float g_z1 [NN * HF];    // relu(agg1 + b1)
__device__ __align__(16) float g_h2 [NN * OUTF];  // z1 @ W2
__device__ unsigned int g_flag;                   // 0 = int64 edge_index, 1 = int32

// ---- software grid barrier (all PREP_G blocks resident by construction) ----
__device__ unsigned g_bar_count = 0;
__device__ volatile unsigned g_bar_gen = 0;

__device__ __forceinline__ void grid_barrier() {
    __syncthreads();
    if (threadIdx.x == 0) {
        unsigned gen = g_bar_gen;
        __threadfence();
        if (atomicAdd(&g_bar_count, 1u) == PREP_G - 1) {
            g_bar_count = 0;
            __threadfence();
            g_bar_gen = gen + 1;
        } else {
            while (g_bar_gen == gen) { }
            __threadfence();
        }
    }
    __syncthreads();
}

// ---------------------------------------------------------------
// GEMM1: H1 = X[NN,128] @ W1[128,64] — with per-call init fused in.
#define G1_SMEM ((128 * 132 + 128 * 64) * 4)

__global__ __launch_bounds__(256) void k_gemm1(const float* __restrict__ x,
                                               const float* __restrict__ W1) {
    extern __shared__ float sh[];
    float* Xs = sh;              // 128 x 132 (pad 4 -> conflict-free)
    float* Ws = sh + 128 * 132;  // 128 x 64

    int nb = blockIdx.x * 128;

    // --- fused init: this block's 128 nodes + (block 0) flag ---
    if (threadIdx.x < 128) {
        int n0 = nb + threadIdx.x;
        if (n0 < NN) {
            g_deg[n0] = 1.0f;    // self-loop weight
            g_cnt[n0] = 0;
            g_cursor[n0] = 0;
        }
    }
    if (blockIdx.x == 0 && threadIdx.x == 0) g_flag = 0u;

    for (int i = threadIdx.x; i < 128 * 64 / 4; i += 256)
        ((float4*)Ws)[i] = ((const float4*)W1)[i];

    for (int i = threadIdx.x; i < 128 * 32; i += 256) {
        int node = i >> 5, k4 = i & 31;
        int gn = nb + node;
        float4 v = make_float4(0.f, 0.f, 0.f, 0.f);
        if (gn < NN) v = ((const float4*)x)[gn * 32 + k4];
        *(float4*)&Xs[node * 132 + k4 * 4] = v;
    }
    __syncthreads();

    int fg = threadIdx.x & 7;   // output group: f = fg*8 .. fg*8+7
    int ng = threadIdx.x >> 3;  // node: ng + 32*j

    float acc[4][8];
#pragma unroll
    for (int j = 0; j < 4; j++)
#pragma unroll
        for (int f = 0; f < 8; f++) acc[j][f] = 0.f;

#pragma unroll 4
    for (int k = 0; k < 128; k++) {
        float xv[4];
#pragma unroll
        for (int j = 0; j < 4; j++) xv[j] = Xs[(ng + 32 * j) * 132 + k];
        float4 wa = *(const float4*)&Ws[k * 64 + fg * 8];
        float4 wb = *(const float4*)&Ws[k * 64 + fg * 8 + 4];
#pragma unroll
        for (int j = 0; j < 4; j++) {
            acc[j][0] += xv[j] * wa.x; acc[j][1] += xv[j] * wa.y;
            acc[j][2] += xv[j] * wa.z; acc[j][3] += xv[j] * wa.w;
            acc[j][4] += xv[j] * wb.x; acc[j][5] += xv[j] * wb.y;
            acc[j][6] += xv[j] * wb.z; acc[j][7] += xv[j] * wb.w;
        }
    }

#pragma unroll
    for (int j = 0; j < 4; j++) {
        int gn = nb + ng + 32 * j;
        if (gn >= NN) continue;
        ((float4*)g_h1)[gn * 16 + fg * 2] =
            make_float4(acc[j][0], acc[j][1], acc[j][2], acc[j][3]);
        ((float4*)g_h1)[gn * 16 + fg * 2 + 1] =
            make_float4(acc[j][4], acc[j][5], acc[j][6], acc[j][7]);
    }
}

// ---------------------------------------------------------------
// prep1: [sample-detect dtype] -> barrier -> decode edges + degree.
// int64 edge_index (values in [0,2^31)): all odd u32 words are 0.
// int32: odd words are col indices; 256 spread samples all being zero has
// probability ~(1e-5)^256 — impossible in practice.
__global__ __launch_bounds__(PREP_B) void k_prep1(const int* __restrict__ ei32,
                                                  const float* __restrict__ ew) {
    if (blockIdx.x == 0) {
        int s = (int)threadIdx.x * (NE / PREP_B) + 1;   // spread samples
        if (((const unsigned int*)ei32)[2 * s + 1] != 0u) atomicOr(&g_flag, 1u);
    }
    grid_barrier();

    int stride = PREP_G * PREP_B;
    int flag = g_flag;
    for (int e = blockIdx.x * PREP_B + threadIdx.x; e < NE; e += stride) {
        int r, c;
        if (flag) {             // int32 layout: [row[NE], col[NE]]
            r = ei32[e];
            c = ei32[NE + e];
        } else {                // int64 layout: low words at even positions
            r = ei32[2 * e];
            c = ei32[2 * (NE + e)];
        }
        g_row[e] = r;
        g_col[e] = c;
        atomicAdd(&g_deg[c], ew[e]);
        atomicAdd(&g_cnt[c], 1);
    }
}

// ---------------------------------------------------------------
// prep2: dinv + local scan -> barrier -> cross-block prefix -> barrier -> CSR fill.
__global__ __launch_bounds__(PREP_B) void k_prep2(const float* __restrict__ ew) {
    int t = threadIdx.x, b = blockIdx.x;
    int lane = t & 31, wid = t >> 5;
    int i = b * NPB + t;                       // NPB=169 < 256
    bool valid = (t < NPB) && (i < NN);

    if (valid) g_dinv[i] = rsqrtf(g_deg[i]);   // deg >= 1 always

    int v = valid ? g_cnt[i] : 0;

    // block scan (shuffle)
    int val = v;
#pragma unroll
    for (int s = 1; s < 32; s <<= 1) {
        int u = __shfl_up_sync(0xffffffffu, val, s);
        if (lane >= s) val += u;
    }
    __shared__ int wsum[8];
    if (lane == 31) wsum[wid] = val;
    __syncthreads();
    __shared__ int wexc[8];
    if (t == 0) {
        int s = 0;
#pragma unroll
        for (int w = 0; w < 8; w++) { wexc[w] = s; s += wsum[w]; }
        g_bsum[b] = s;                          // block total
    }
    __syncthreads();
    int excl = wexc[wid] + val - v;
    if (valid) g_off[i] = excl;                 // local exclusive (prefix later)

    grid_barrier();

    // cross-block prefix: sum of g_bsum[j] for j < b (each block redundantly)
    __shared__ int red[PREP_B];
    int p = 0;
    for (int j = t; j < b; j += PREP_B) p += g_bsum[j];
    red[t] = p;
    __syncthreads();
#pragma unroll
    for (int s = 128; s > 0; s >>= 1) {
        if (t < s) red[t] += red[t + s];
        __syncthreads();
    }
    int prefix = red[0];
    if (valid) g_off[i] += prefix;
    if (b == 0 && t == 0) g_off[NN] = NE;

    grid_barrier();

    // CSR fill with fused norm; packed (row, norm) int2.
    int stride = PREP_G * PREP_B;
    for (int e = b * PREP_B + t; e < NE; e += stride) {
        int r = g_row[e], c = g_col[e];
        int pos = g_off[c] + atomicAdd(&g_cursor[c], 1);
        float nm = g_dinv[r] * ew[e] * g_dinv[c];
        g_csr[pos] = make_int2(r, __float_as_int(nm));
    }
}

// ---------------------------------------------------------------
// Gather layer 1: 16-lane group per node, float4 per lane (row = 16 x float4).
// z1 = relu(b1 + dinv^2*H1[c] + sum_e norm_e * H1[row_e]).  Unroll x4.
__global__ __launch_bounds__(256) void k_gather1(const float* __restrict__ b1) {
    int tid = blockIdx.x * 256 + threadIdx.x;
    int c = tid >> 4;
    int sub = threadIdx.x & 15;
    if (c >= NN) return;

    const float4* H = (const float4*)g_h1;     // row stride 16
    float di = g_dinv[c];
    float d2 = di * di;
    float4 hc = H[c * 16 + sub];
    float ax = d2 * hc.x, ay = d2 * hc.y, az = d2 * hc.z, aw = d2 * hc.w;

    int i = g_off[c], end = g_off[c + 1];
    for (; i + 3 < end; i += 4) {
        int2 e0 = g_csr[i],     e1 = g_csr[i + 1];
        int2 e2 = g_csr[i + 2], e3 = g_csr[i + 3];
        float4 h0 = H[e0.x * 16 + sub];
        float4 h1 = H[e1.x * 16 + sub];
        float4 h2 = H[e2.x * 16 + sub];
        float4 h3 = H[e3.x * 16 + sub];
        float n0 = __int_as_float(e0.y), n1 = __int_as_float(e1.y);
        float n2 = __int_as_float(e2.y), n3 = __int_as_float(e3.y);
        ax += n0 * h0.x + n1 * h1.x + n2 * h2.x + n3 * h3.x;
        ay += n0 * h0.y + n1 * h1.y + n2 * h2.y + n3 * h3.y;
        az += n0 * h0.z + n1 * h1.z + n2 * h2.z + n3 * h3.z;
        aw += n0 * h0.w + n1 * h1.w + n2 * h2.w + n3 * h3.w;
    }
    for (; i < end; i++) {
        int2 e0 = g_csr[i];
        float4 h0 = H[e0.x * 16 + sub];
        float n0 = __int_as_float(e0.y);
        ax += n0 * h0.x; ay += n0 * h0.y; az += n0 * h0.z; aw += n0 * h0.w;
    }

    float4 bb = ((const float4*)b1)[sub];
    float4 z;
    z.x = fmaxf(ax + bb.x, 0.f);
    z.y = fmaxf(ay + bb.y, 0.f);
    z.z = fmaxf(az + bb.z, 0.f);
    z.w = fmaxf(aw + bb.w, 0.f);
    ((float4*)g_z1)[c * 16 + sub] = z;
}

// ---------------------------------------------------------------
// GEMM2: H2 = z1[NN,64] @ W2[64,32]
__global__ __launch_bounds__(256) void k_gemm2(const float* __restrict__ W2) {
    __shared__ float Xs[128 * 68];  // 128 x (64+4)
    __shared__ float Ws[64 * 32];

    int nb = blockIdx.x * 128;

    for (int i = threadIdx.x; i < 64 * 32 / 4; i += 256)
        ((float4*)Ws)[i] = ((const float4*)W2)[i];

    for (int i = threadIdx.x; i < 128 * 16; i += 256) {
        int node = i >> 4, k4 = i & 15;
        int gn = nb + node;
        float4 v = make_float4(0.f, 0.f, 0.f, 0.f);
        if (gn < NN) v = ((const float4*)g_z1)[gn * 16 + k4];
        *(float4*)&Xs[node * 68 + k4 * 4] = v;
    }
    __syncthreads();

    int fg = threadIdx.x & 7;   // f = fg*4 .. fg*4+3
    int ng = threadIdx.x >> 3;  // node: ng + 32*j

    float acc[4][4];
#pragma unroll
    for (int j = 0; j < 4; j++)
#pragma unroll
        for (int f = 0; f < 4; f++) acc[j][f] = 0.f;

#pragma unroll 4
    for (int k = 0; k < 64; k++) {
        float xv[4];
#pragma unroll
        for (int j = 0; j < 4; j++) xv[j] = Xs[(ng + 32 * j) * 68 + k];
        float4 w = *(const float4*)&Ws[k * 32 + fg * 4];
#pragma unroll
        for (int j = 0; j < 4; j++) {
            acc[j][0] += xv[j] * w.x; acc[j][1] += xv[j] * w.y;
            acc[j][2] += xv[j] * w.z; acc[j][3] += xv[j] * w.w;
        }
    }

#pragma unroll
    for (int j = 0; j < 4; j++) {
        int gn = nb + ng + 32 * j;
        if (gn >= NN) continue;
        ((float4*)g_h2)[gn * 8 + fg] =
            make_float4(acc[j][0], acc[j][1], acc[j][2], acc[j][3]);
    }
}

// ---------------------------------------------------------------
// Gather layer 2: 8-lane group per node, float4 per lane (row = 8 x float4).
// out = b2 + dinv^2*H2[c] + sum_e norm_e * H2[row_e].  Unroll x4.
__global__ __launch_bounds__(256) void k_gather2(const float* __restrict__ b2,
                                                 float* __restrict__ out) {
    int tid = blockIdx.x * 256 + threadIdx.x;
    int c = tid >> 3;
    int sub = threadIdx.x & 7;
    if (c >= NN) return;

    const float4* H = (const float4*)g_h2;     // row stride 8
    float di = g_dinv[c];
    float d2 = di * di;
    float4 hc = H[c * 8 + sub];
    float ax = d2 * hc.x, ay = d2 * hc.y, az = d2 * hc.z, aw = d2 * hc.w;

    int i = g_off[c], end = g_off[c + 1];
    for (; i + 3 < end; i += 4) {
        int2 e0 = g_csr[i],     e1 = g_csr[i + 1];
        int2 e2 = g_csr[i + 2], e3 = g_csr[i + 3];
        float4 h0 = H[e0.x * 8 + sub];
        float4 h1 = H[e1.x * 8 + sub];
        float4 h2 = H[e2.x * 8 + sub];
        float4 h3 = H[e3.x * 8 + sub];
        float n0 = __int_as_float(e0.y), n1 = __int_as_float(e1.y);
        float n2 = __int_as_float(e2.y), n3 = __int_as_float(e3.y);
        ax += n0 * h0.x + n1 * h1.x + n2 * h2.x + n3 * h3.x;
        ay += n0 * h0.y + n1 * h1.y + n2 * h2.y + n3 * h3.y;
        az += n0 * h0.z + n1 * h1.z + n2 * h2.z + n3 * h3.z;
        aw += n0 * h0.w + n1 * h1.w + n2 * h2.w + n3 * h3.w;
    }
    for (; i < end; i++) {
        int2 e0 = g_csr[i];
        float4 h0 = H[e0.x * 8 + sub];
        float n0 = __int_as_float(e0.y);
        ax += n0 * h0.x; ay += n0 * h0.y; az += n0 * h0.z; aw += n0 * h0.w;
    }

    float4 bb = ((const float4*)b2)[sub];
    ((float4*)out)[c * 8 + sub] =
        make_float4(ax + bb.x, ay + bb.y, az + bb.z, aw + bb.w);
}

// ---------------------------------------------------------------
static const void* by_size(void* const* d_in, const int* in_sizes, int n_in,
                           long long want) {
    for (int i = 0; i < n_in; i++)
        if ((long long)in_sizes[i] == want) return d_in[i];
    return 0;
}

extern "C" void kernel_launch(void* const* d_in, const int* in_sizes, int n_in,
                              void* d_out, int out_size) {
    // Match inputs by (distinct) element counts — immune to ordering surprises.
    const float* x  = (const float*)by_size(d_in, in_sizes, n_in, (long long)NN * INF);   // 12.8M
    const void*  ei =               by_size(d_in, in_sizes, n_in, 2LL * NE);              // 3.2M
    const float* ew = (const float*)by_size(d_in, in_sizes, n_in, (long long)NE);         // 1.6M
    const float* W1 = (const float*)by_size(d_in, in_sizes, n_in, (long long)INF * HF);   // 8192
    const float* b1 = (const float*)by_size(d_in, in_sizes, n_in, (long long)HF);         // 64
    const float* W2 = (const float*)by_size(d_in, in_sizes, n_in, (long long)HF * OUTF);  // 2048
    const float* b2 = (const float*)by_size(d_in, in_sizes, n_in, (long long)OUTF);       // 32
    float* out = (float*)d_out;

    cudaFuncSetAttribute(k_gemm1, cudaFuncAttributeMaxDynamicSharedMemorySize, G1_SMEM);

    // Profiled launch is the 4th of this sequence -> k_gather1.
    k_gemm1  <<<(NN + 127) / 128, 256, G1_SMEM>>>(x, W1);    // 1 (+init)
    k_prep1  <<<PREP_G, PREP_B>>>((const int*)ei, ew);       // 2
    k_prep2  <<<PREP_G, PREP_B>>>(ew);                       // 3
    k_gather1<<<(NN * 16 + 255) / 256, 256>>>(b1);           // 4 <- profiled
    k_gemm2  <<<(NN + 127) / 128, 256>>>(W2);                // 5
    k_gather2<<<(NN * 8 + 255) / 256, 256>>>(b2, out);       // 6
}

// round 7
// speedup vs baseline: 2.0921x; 1.0438x over previous
#include <cuda_runtime.h>

#define NN   100000
#define NE   1600000
#define INF  128
#define HF   64
#define OUTF 32

#define PREP_B   256
#define PREP_G   592                      // 4 per SM on 148 SMs: all co-resident
#define NPB      ((NN + PREP_G - 1) / PREP_G)   // 169 nodes per block

// ---- scratch (static device globals; no allocation anywhere) ----
__device__ __align__(16) float g_deg   [NN];
__device__ __align__(16) float g_dinv  [NN];
__device__ __align__(16) int   g_cnt   [NN];      // in-degree histogram (by col)
__device__ __align__(16) int   g_cursor[NN];      // CSR fill cursors
__device__ __align__(16) int   g_off   [NN + 1];  // CSR offsets (exclusive)
__device__ __align__(16) int   g_bsum  [PREP_G];  // per-block count totals
__device__ __align__(16) int2  g_csr   [NE];      // packed (src_row, norm-bits)
__device__ __align__(16) float g_h1 [NN * HF];    // X @ W1
__device__ __align__(16) float g_z1 [NN * HF];    // relu(agg1 + b1)
__device__ __align__(16) float g_h2 [NN * OUTF];  // z1 @ W2
__device__ unsigned int g_flag;                   // 0 = int64 edge_index, 1 = int32

// ---- packed f32x2 helpers (Blackwell FFMA2) ----
__device__ __forceinline__ unsigned long long pack2(float x) {
    unsigned long long r;
    asm("mov.b64 %0, {%1, %2};" : "=l"(r) : "f"(x), "f"(x));
    return r;
}
__device__ __forceinline__ unsigned long long fma2(unsigned long long a,
                                                   unsigned long long b,
                                                   unsigned long long c) {
    unsigned long long d;
    asm("fma.rn.f32x2 %0, %1, %2, %3;" : "=l"(d) : "l"(a), "l"(b), "l"(c));
    return d;
}
__device__ __forceinline__ float2 unpack2(unsigned long long v) {
    float lo, hi;
    asm("mov.b64 {%0, %1}, %2;" : "=f"(lo), "=f"(hi) : "l"(v));
    return make_float2(lo, hi);
}

// ---- software grid barrier (all PREP_G blocks resident by construction) ----
__device__ unsigned g_bar_count = 0;
__device__ volatile unsigned g_bar_gen = 0;

__device__ __forceinline__ void grid_barrier() {
    __syncthreads();
    if (threadIdx.x == 0) {
        unsigned gen = g_bar_gen;
        __threadfence();
        if (atomicAdd(&g_bar_count, 1u) == PREP_G - 1) {
            g_bar_count = 0;
            __threadfence();
            g_bar_gen = gen + 1;
        } else {
            while (g_bar_gen == gen) { }
            __threadfence();
        }
    }
    __syncthreads();
}

// ---------------------------------------------------------------
// k_init: per-call scratch init + sampled dtype detect.
// int64 edge_index (values in [0,2^31)): all odd u32 words are 0.
// int32: odd words are col indices; 256 spread samples all being zero has
// probability ~(1e-5)^256 — impossible in practice.
__global__ void k_init(const unsigned int* __restrict__ ei32) {
    int i = blockIdx.x * 256 + threadIdx.x;
    if (i < NN) {
        g_deg[i] = 1.0f;    // self-loop weight
        g_cnt[i] = 0;
        g_cursor[i] = 0;
    }
    if (blockIdx.x == 0) {
        if (threadIdx.x == 0) g_flag = 0u;
        __syncthreads();
        int s = (int)threadIdx.x * (NE / 256) + 1;   // spread samples
        if (ei32[2 * s + 1] != 0u) atomicOr(&g_flag, 1u);
    }
}

// prep1: decode edges + degree/count atomics (flag set by k_init launch).
__global__ __launch_bounds__(PREP_B) void k_prep1(const int* __restrict__ ei32,
                                                  const float* __restrict__ ew) {
    int stride = PREP_G * PREP_B;
    int flag = g_flag;
    for (int e = blockIdx.x * PREP_B + threadIdx.x; e < NE; e += stride) {
        int c;
        if (flag) c = ei32[NE + e];          // int32: [row[NE], col[NE]]
        else      c = ei32[2 * (NE + e)];    // int64: low word
        atomicAdd(&g_deg[c], ew[e]);
        atomicAdd(&g_cnt[c], 1);
    }
}

// prep2: dinv + local scan -> barrier -> cross-block prefix -> barrier -> fill.
__global__ __launch_bounds__(PREP_B) void k_prep2(const int* __restrict__ ei32,
                                                  const float* __restrict__ ew) {
    int t = threadIdx.x, b = blockIdx.x;
    int lane = t & 31, wid = t >> 5;
    int i = b * NPB + t;                       // NPB=169 < 256
    bool valid = (t < NPB) && (i < NN);

    if (valid) g_dinv[i] = rsqrtf(g_deg[i]);   // deg >= 1 always

    int v = valid ? g_cnt[i] : 0;

    // block scan (shuffle)
    int val = v;
#pragma unroll
    for (int s = 1; s < 32; s <<= 1) {
        int u = __shfl_up_sync(0xffffffffu, val, s);
        if (lane >= s) val += u;
    }
    __shared__ int wsum[8];
    if (lane == 31) wsum[wid] = val;
    __syncthreads();
    __shared__ int wexc[8];
    if (t == 0) {
        int s = 0;
#pragma unroll
        for (int w = 0; w < 8; w++) { wexc[w] = s; s += wsum[w]; }
        g_bsum[b] = s;                          // block total
    }
    __syncthreads();
    int excl = wexc[wid] + val - v;
    if (valid) g_off[i] = excl;                 // local exclusive (prefix later)

    grid_barrier();

    // cross-block prefix: sum of g_bsum[j] for j < b (each block redundantly)
    __shared__ int red[PREP_B];
    int p = 0;
    for (int j = t; j < b; j += PREP_B) p += g_bsum[j];
    red[t] = p;
    __syncthreads();
#pragma unroll
    for (int s = 128; s > 0; s >>= 1) {
        if (t < s) red[t] += red[t + s];
        __syncthreads();
    }
    int prefix = red[0];
    if (valid) g_off[i] += prefix;
    if (b == 0 && t == 0) g_off[NN] = NE;

    grid_barrier();

    // CSR fill with fused norm; packed (row, norm) int2. Re-decode edges.
    int stride = PREP_G * PREP_B;
    int flag = g_flag;
    for (int e = b * PREP_B + t; e < NE; e += stride) {
        int r, c;
        if (flag) { r = ei32[e];     c = ei32[NE + e]; }
        else      { r = ei32[2 * e]; c = ei32[2 * (NE + e)]; }
        int pos = g_off[c] + atomicAdd(&g_cursor[c], 1);
        float nm = g_dinv[r] * ew[e] * g_dinv[c];
        g_csr[pos] = make_int2(r, __float_as_int(nm));
    }
}

// ---------------------------------------------------------------
// GEMM1: H1 = X[NN,128] @ W1[128,64], packed f32x2 FMAs.
// tile: 128 nodes/block, 256 threads; thread = 4 nodes x 4 output-pairs.
#define G1_SMEM ((128 * 132 + 128 * 64) * 4)

__global__ __launch_bounds__(256) void k_gemm1(const float* __restrict__ x,
                                               const float* __restrict__ W1) {
    extern __shared__ float sh[];
    float* Xs = sh;              // 128 x 132 (pad 4 -> conflict-free)
    float* Ws = sh + 128 * 132;  // 128 x 64 (offset 67584B: 16B aligned)

    int nb = blockIdx.x * 128;

    for (int i = threadIdx.x; i < 128 * 64 / 4; i += 256)
        ((float4*)Ws)[i] = ((const float4*)W1)[i];

    for (int i = threadIdx.x; i < 128 * 32; i += 256) {
        int node = i >> 5, k4 = i & 31;
        int gn = nb + node;
        float4 v = make_float4(0.f, 0.f, 0.f, 0.f);
        if (gn < NN) v = ((const float4*)x)[gn * 32 + k4];
        *(float4*)&Xs[node * 132 + k4 * 4] = v;
    }
    __syncthreads();

    int fg = threadIdx.x & 7;   // output group: f = fg*8 .. fg*8+7 (4 pairs)
    int ng = threadIdx.x >> 3;  // node: ng + 32*j

    unsigned long long acc[4][4];   // [node][output-pair]
#pragma unroll
    for (int j = 0; j < 4; j++)
#pragma unroll
        for (int p = 0; p < 4; p++) acc[j][p] = 0ull;

#pragma unroll 4
    for (int k = 0; k < 128; k++) {
        unsigned long long xd[4];
#pragma unroll
        for (int j = 0; j < 4; j++) xd[j] = pack2(Xs[(ng + 32 * j) * 132 + k]);
        ulonglong2 wa = *(const ulonglong2*)&Ws[k * 64 + fg * 8];
        ulonglong2 wb = *(const ulonglong2*)&Ws[k * 64 + fg * 8 + 4];
#pragma unroll
        for (int j = 0; j < 4; j++) {
            acc[j][0] = fma2(xd[j], wa.x, acc[j][0]);
            acc[j][1] = fma2(xd[j], wa.y, acc[j][1]);
            acc[j][2] = fma2(xd[j], wb.x, acc[j][2]);
            acc[j][3] = fma2(xd[j], wb.y, acc[j][3]);
        }
    }

#pragma unroll
    for (int j = 0; j < 4; j++) {
        int gn = nb + ng + 32 * j;
        if (gn >= NN) continue;
        float2 p0 = unpack2(acc[j][0]), p1 = unpack2(acc[j][1]);
        float2 p2 = unpack2(acc[j][2]), p3 = unpack2(acc[j][3]);
        ((float4*)g_h1)[gn * 16 + fg * 2]     = make_float4(p0.x, p0.y, p1.x, p1.y);
        ((float4*)g_h1)[gn * 16 + fg * 2 + 1] = make_float4(p2.x, p2.y, p3.x, p3.y);
    }
}

// ---------------------------------------------------------------
// Gather layer 1: 16-lane group per node, float4 per lane (row = 16 x float4).
// z1 = relu(b1 + dinv^2*H1[c] + sum_e norm_e * H1[row_e]).  Unroll x4.
__global__ __launch_bounds__(256) void k_gather1(const float* __restrict__ b1) {
    int tid = blockIdx.x * 256 + threadIdx.x;
    int c = tid >> 4;
    int sub = threadIdx.x & 15;
    if (c >= NN) return;

    const float4* H = (const float4*)g_h1;     // row stride 16
    float di = g_dinv[c];
    float d2 = di * di;
    float4 hc = H[c * 16 + sub];
    float ax = d2 * hc.x, ay = d2 * hc.y, az = d2 * hc.z, aw = d2 * hc.w;

    int i = g_off[c], end = g_off[c + 1];
    for (; i + 3 < end; i += 4) {
        int2 e0 = g_csr[i],     e1 = g_csr[i + 1];
        int2 e2 = g_csr[i + 2], e3 = g_csr[i + 3];
        float4 h0 = H[e0.x * 16 + sub];
        float4 h1 = H[e1.x * 16 + sub];
        float4 h2 = H[e2.x * 16 + sub];
        float4 h3 = H[e3.x * 16 + sub];
        float n0 = __int_as_float(e0.y), n1 = __int_as_float(e1.y);
        float n2 = __int_as_float(e2.y), n3 = __int_as_float(e3.y);
        ax += n0 * h0.x + n1 * h1.x + n2 * h2.x + n3 * h3.x;
        ay += n0 * h0.y + n1 * h1.y + n2 * h2.y + n3 * h3.y;
        az += n0 * h0.z + n1 * h1.z + n2 * h2.z + n3 * h3.z;
        aw += n0 * h0.w + n1 * h1.w + n2 * h2.w + n3 * h3.w;
    }
    for (; i < end; i++) {
        int2 e0 = g_csr[i];
        float4 h0 = H[e0.x * 16 + sub];
        float n0 = __int_as_float(e0.y);
        ax += n0 * h0.x; ay += n0 * h0.y; az += n0 * h0.z; aw += n0 * h0.w;
    }

    float4 bb = ((const float4*)b1)[sub];
    float4 z;
    z.x = fmaxf(ax + bb.x, 0.f);
    z.y = fmaxf(ay + bb.y, 0.f);
    z.z = fmaxf(az + bb.z, 0.f);
    z.w = fmaxf(aw + bb.w, 0.f);
    ((float4*)g_z1)[c * 16 + sub] = z;
}

// ---------------------------------------------------------------
// GEMM2: H2 = z1[NN,64] @ W2[64,32], packed f32x2 FMAs.
__global__ __launch_bounds__(256) void k_gemm2(const float* __restrict__ W2) {
    __shared__ __align__(16) float Xs[128 * 68];  // 128 x (64+4)
    __shared__ __align__(16) float Ws[64 * 32];

    int nb = blockIdx.x * 128;

    for (int i = threadIdx.x; i < 64 * 32 / 4; i += 256)
        ((float4*)Ws)[i] = ((const float4*)W2)[i];

    for (int i = threadIdx.x; i < 128 * 16; i += 256) {
        int node = i >> 4, k4 = i & 15;
        int gn = nb + node;
        float4 v = make_float4(0.f, 0.f, 0.f, 0.f);
        if (gn < NN) v = ((const float4*)g_z1)[gn * 16 + k4];
        *(float4*)&Xs[node * 68 + k4 * 4] = v;
    }
    __syncthreads();

    int fg = threadIdx.x & 7;   // f = fg*4 .. fg*4+3 (2 pairs)
    int ng = threadIdx.x >> 3;  // node: ng + 32*j

    unsigned long long acc[4][2];
#pragma unroll
    for (int j = 0; j < 4; j++) { acc[j][0] = 0ull; acc[j][1] = 0ull; }

#pragma unroll 4
    for (int k = 0; k < 64; k++) {
        unsigned long long xd[4];
#pragma unroll
        for (int j = 0; j < 4; j++) xd[j] = pack2(Xs[(ng + 32 * j) * 68 + k]);
        ulonglong2 w = *(const ulonglong2*)&Ws[k * 32 + fg * 4];
#pragma unroll
        for (int j = 0; j < 4; j++) {
            acc[j][0] = fma2(xd[j], w.x, acc[j][0]);
            acc[j][1] = fma2(xd[j], w.y, acc[j][1]);
        }
    }

#pragma unroll
    for (int j = 0; j < 4; j++) {
        int gn = nb + ng + 32 * j;
        if (gn >= NN) continue;
        float2 p0 = unpack2(acc[j][0]), p1 = unpack2(acc[j][1]);
        ((float4*)g_h2)[gn * 8 + fg] = make_float4(p0.x, p0.y, p1.x, p1.y);
    }
}

// ---------------------------------------------------------------
// Gather layer 2: 8-lane group per node, float4 per lane (row = 8 x float4).
// out = b2 + dinv^2*H2[c] + sum_e norm_e * H2[row_e].  Unroll x4.
__global__ __launch_bounds__(256) void k_gather2(const float* __restrict__ b2,
                                                 float* __restrict__ out) {
    int tid = blockIdx.x * 256 + threadIdx.x;
    int c = tid >> 3;
    int sub = threadIdx.x & 7;
    if (c >= NN) return;

    const float4* H = (const float4*)g_h2;     // row stride 8
    float di = g_dinv[c];
    float d2 = di * di;
    float4 hc = H[c * 8 + sub];
    float ax = d2 * hc.x, ay = d2 * hc.y, az = d2 * hc.z, aw = d2 * hc.w;

    int i = g_off[c], end = g_off[c + 1];
    for (; i + 3 < end; i += 4) {
        int2 e0 = g_csr[i],     e1 = g_csr[i + 1];
        int2 e2 = g_csr[i + 2], e3 = g_csr[i + 3];
        float4 h0 = H[e0.x * 8 + sub];
        float4 h1 = H[e1.x * 8 + sub];
        float4 h2 = H[e2.x * 8 + sub];
        float4 h3 = H[e3.x * 8 + sub];
        float n0 = __int_as_float(e0.y), n1 = __int_as_float(e1.y);
        float n2 = __int_as_float(e2.y), n3 = __int_as_float(e3.y);
        ax += n0 * h0.x + n1 * h1.x + n2 * h2.x + n3 * h3.x;
        ay += n0 * h0.y + n1 * h1.y + n2 * h2.y + n3 * h3.y;
        az += n0 * h0.z + n1 * h1.z + n2 * h2.z + n3 * h3.z;
        aw += n0 * h0.w + n1 * h1.w + n2 * h2.w + n3 * h3.w;
    }
    for (; i < end; i++) {
        int2 e0 = g_csr[i];
        float4 h0 = H[e0.x * 8 + sub];
        float n0 = __int_as_float(e0.y);
        ax += n0 * h0.x; ay += n0 * h0.y; az += n0 * h0.z; aw += n0 * h0.w;
    }

    float4 bb = ((const float4*)b2)[sub];
    ((float4*)out)[c * 8 + sub] =
        make_float4(ax + bb.x, ay + bb.y, az + bb.z, aw + bb.w);
}

// ---------------------------------------------------------------
static const void* by_size(void* const* d_in, const int* in_sizes, int n_in,
                           long long want) {
    for (int i = 0; i < n_in; i++)
        if ((long long)in_sizes[i] == want) return d_in[i];
    return 0;
}

extern "C" void kernel_launch(void* const* d_in, const int* in_sizes, int n_in,
                              void* d_out, int out_size) {
    // Match inputs by (distinct) element counts — immune to ordering surprises.
    const float* x  = (const float*)by_size(d_in, in_sizes, n_in, (long long)NN * INF);   // 12.8M
    const void*  ei =               by_size(d_in, in_sizes, n_in, 2LL * NE);              // 3.2M
    const float* ew = (const float*)by_size(d_in, in_sizes, n_in, (long long)NE);         // 1.6M
    const float* W1 = (const float*)by_size(d_in, in_sizes, n_in, (long long)INF * HF);   // 8192
    const float* b1 = (const float*)by_size(d_in, in_sizes, n_in, (long long)HF);         // 64
    const float* W2 = (const float*)by_size(d_in, in_sizes, n_in, (long long)HF * OUTF);  // 2048
    const float* b2 = (const float*)by_size(d_in, in_sizes, n_in, (long long)OUTF);       // 32
    float* out = (float*)d_out;

    cudaFuncSetAttribute(k_gemm1, cudaFuncAttributeMaxDynamicSharedMemorySize, G1_SMEM);

    // Profiled launch is the 4th of this sequence -> k_gemm1 (verify FFMA2).
    k_init   <<<(NN + 255) / 256, 256>>>((const unsigned int*)ei);  // 1
    k_prep1  <<<PREP_G, PREP_B>>>((const int*)ei, ew);              // 2
    k_prep2  <<<PREP_G, PREP_B>>>((const int*)ei, ew);              // 3
    k_gemm1  <<<(NN + 127) / 128, 256, G1_SMEM>>>(x, W1);           // 4 <- profiled
    k_gather1<<<(NN * 16 + 255) / 256, 256>>>(b1);                  // 5
    k_gemm2  <<<(NN + 127) / 128, 256>>>(W2);                       // 6
    k_gather2<<<(NN * 8 + 255) / 256, 256>>>(b2, out);              // 7
}

// round 8
// speedup vs baseline: 2.4562x; 1.1740x over previous
#include <cuda_runtime.h>

#define NN   100000
#define NE   1600000
#define INF  128
#define HF   64
#define OUTF 32

#define PREP_B   256
#define PREP_G   592                      // 4 per SM on 148 SMs: all co-resident
#define NPB      ((NN + PREP_G - 1) / PREP_G)   // 169 nodes per block

// ---- scratch (static device globals; no allocation anywhere) ----
__device__ __align__(16) float g_deg   [NN];
__device__ __align__(16) float g_dinv  [NN];
__device__ __align__(16) int   g_cnt   [NN];      // in-degree histogram (by col)
__device__ __align__(16) int   g_cursor[NN];      // CSR fill cursors
__device__ __align__(16) int   g_off   [NN + 1];  // CSR offsets (exclusive)
__device__ __align__(16) int   g_bsum  [PREP_G];  // per-block count totals
__device__ __align__(16) int2  g_csr   [NE];      // packed (src_row, norm-bits)
__device__ __align__(16) float g_h1 [NN * HF];    // X @ W1
__device__ __align__(16) float g_z1 [NN * HF];    // relu(agg1 + b1)
__device__ __align__(16) float g_h2 [NN * OUTF];  // z1 @ W2
__device__ unsigned int g_flag;                   // 0 = int64 edge_index, 1 = int32

// ---- packed f32x2 helpers (Blackwell FFMA2) ----
__device__ __forceinline__ unsigned long long pack2(float x) {
    unsigned long long r;
    asm("mov.b64 %0, {%1, %2};" : "=l"(r) : "f"(x), "f"(x));
    return r;
}
__device__ __forceinline__ unsigned long long fma2(unsigned long long a,
                                                   unsigned long long b,
                                                   unsigned long long c) {
    unsigned long long d;
    asm("fma.rn.f32x2 %0, %1, %2, %3;" : "=l"(d) : "l"(a), "l"(b), "l"(c));
    return d;
}
__device__ __forceinline__ float2 unpack2(unsigned long long v) {
    float lo, hi;
    asm("mov.b64 {%0, %1}, %2;" : "=f"(lo), "=f"(hi) : "l"(v));
    return make_float2(lo, hi);
}

// ---- software grid barrier (all PREP_G blocks resident by construction) ----
__device__ unsigned g_bar_count = 0;
__device__ volatile unsigned g_bar_gen = 0;

__device__ __forceinline__ void grid_barrier() {
    __syncthreads();
    if (threadIdx.x == 0) {
        unsigned gen = g_bar_gen;
        __threadfence();
        if (atomicAdd(&g_bar_count, 1u) == PREP_G - 1) {
            g_bar_count = 0;
            __threadfence();
            g_bar_gen = gen + 1;
        } else {
            while (g_bar_gen == gen) { }
            __threadfence();
        }
    }
    __syncthreads();
}

// ---------------------------------------------------------------
// k_init: per-call scratch init + sampled dtype detect.
__global__ void k_init(const unsigned int* __restrict__ ei32) {
    int i = blockIdx.x * 256 + threadIdx.x;
    if (i < NN) {
        g_deg[i] = 1.0f;    // self-loop weight
        g_cnt[i] = 0;
        g_cursor[i] = 0;
    }
    if (blockIdx.x == 0) {
        if (threadIdx.x == 0) g_flag = 0u;
        __syncthreads();
        int s = (int)threadIdx.x * (NE / 256) + 1;   // spread samples
        if (ei32[2 * s + 1] != 0u) atomicOr(&g_flag, 1u);
    }
}

// prep1: decode edges + degree/count atomics (flag set by k_init launch).
__global__ __launch_bounds__(PREP_B) void k_prep1(const int* __restrict__ ei32,
                                                  const float* __restrict__ ew) {
    int stride = PREP_G * PREP_B;
    int flag = g_flag;
    for (int e = blockIdx.x * PREP_B + threadIdx.x; e < NE; e += stride) {
        int c;
        if (flag) c = ei32[NE + e];          // int32: [row[NE], col[NE]]
        else      c = ei32[2 * (NE + e)];    // int64: low word
        atomicAdd(&g_deg[c], ew[e]);
        atomicAdd(&g_cnt[c], 1);
    }
}

// prep2: dinv + local scan -> barrier -> cross-block prefix -> barrier -> fill.
__global__ __launch_bounds__(PREP_B) void k_prep2(const int* __restrict__ ei32,
                                                  const float* __restrict__ ew) {
    int t = threadIdx.x, b = blockIdx.x;
    int lane = t & 31, wid = t >> 5;
    int i = b * NPB + t;                       // NPB=169 < 256
    bool valid = (t < NPB) && (i < NN);

    if (valid) g_dinv[i] = rsqrtf(g_deg[i]);   // deg >= 1 always

    int v = valid ? g_cnt[i] : 0;

    // block scan (shuffle)
    int val = v;
#pragma unroll
    for (int s = 1; s < 32; s <<= 1) {
        int u = __shfl_up_sync(0xffffffffu, val, s);
        if (lane >= s) val += u;
    }
    __shared__ int wsum[8];
    if (lane == 31) wsum[wid] = val;
    __syncthreads();
    __shared__ int wexc[8];
    if (t == 0) {
        int s = 0;
#pragma unroll
        for (int w = 0; w < 8; w++) { wexc[w] = s; s += wsum[w]; }
        g_bsum[b] = s;                          // block total
    }
    __syncthreads();
    int excl = wexc[wid] + val - v;
    if (valid) g_off[i] = excl;                 // local exclusive (prefix later)

    grid_barrier();

    // cross-block prefix: sum of g_bsum[j] for j < b (each block redundantly)
    __shared__ int red[PREP_B];
    int p = 0;
    for (int j = t; j < b; j += PREP_B) p += g_bsum[j];
    red[t] = p;
    __syncthreads();
#pragma unroll
    for (int s = 128; s > 0; s >>= 1) {
        if (t < s) red[t] += red[t + s];
        __syncthreads();
    }
    int prefix = red[0];
    if (valid) g_off[i] += prefix;
    if (b == 0 && t == 0) g_off[NN] = NE;

    grid_barrier();

    // CSR fill with fused norm; packed (row, norm) int2. Re-decode edges.
    int stride = PREP_G * PREP_B;
    int flag = g_flag;
    for (int e = b * PREP_B + t; e < NE; e += stride) {
        int r, c;
        if (flag) { r = ei32[e];     c = ei32[NE + e]; }
        else      { r = ei32[2 * e]; c = ei32[2 * (NE + e)]; }
        int pos = g_off[c] + atomicAdd(&g_cursor[c], 1);
        float nm = g_dinv[r] * ew[e] * g_dinv[c];
        g_csr[pos] = make_int2(r, __float_as_int(nm));
    }
}

// ---------------------------------------------------------------
// GEMM1: H1 = X[NN,128] @ W1[128,64], FFMA2, fma-bound design.
// 256 nodes/block, 256 threads; thread = 8 nodes (j*32+ng) x 8 outputs (4 pairs).
// X staged in 2 k-stages of 64 (Xs 256x68), W in conflict-free layout
// Wsh[fg*1028 + k*8 + p] -> per-warp W LDS.128 is 1 phase (banks 4fg+8k).
#define G1_XS    (256 * 68)                    // floats, 69632 B
#define G1_WS    (8 * 1028)                    //  8224 floats, 32896 B
#define G1_SMEM  ((G1_XS + G1_WS) * 4)         // 102528 B

__global__ __launch_bounds__(256, 2) void k_gemm1(const float* __restrict__ x,
                                                  const float* __restrict__ W1) {
    extern __shared__ float sh[];
    float* Xs  = sh;           // [256][68]
    float* Wsh = sh + G1_XS;   // [8][1028]  (fg-major, 8 floats per k, pad 4)

    int nb = blockIdx.x * 256;
    int tid = threadIdx.x;
    int fg = tid & 7;          // output pairs: f = fg*8 .. fg*8+7
    int ng = tid >> 3;         // 0..31; nodes: j*32 + ng

    // Load W1 (128x64) into swizzled layout.
    for (int i = tid; i < 128 * 16; i += 256) {
        int k = i >> 4, c = i & 15;            // c = float4 index in row
        int fgw = c >> 1, half = (c & 1) * 4;
        float4 v = ((const float4*)W1)[i];
        *(float4*)&Wsh[fgw * 1028 + k * 8 + half] = v;
    }

    unsigned long long acc[8][4];
#pragma unroll
    for (int j = 0; j < 8; j++)
#pragma unroll
        for (int p = 0; p < 4; p++) acc[j][p] = 0ull;

#pragma unroll
    for (int stage = 0; stage < 2; stage++) {
        // stage k-range: [stage*64, stage*64+64)
        for (int i = tid; i < 256 * 16; i += 256) {
            int node = i >> 4, kc = i & 15;
            int gn = nb + node;
            float4 v = make_float4(0.f, 0.f, 0.f, 0.f);
            if (gn < NN) v = ((const float4*)x)[gn * 32 + stage * 16 + kc];
            *(float4*)&Xs[node * 68 + kc * 4] = v;
        }
        __syncthreads();

#pragma unroll 2
        for (int kc = 0; kc < 16; kc++) {      // 4 k per iter
            float4 xv[8];
#pragma unroll
            for (int j = 0; j < 8; j++)
                xv[j] = ((const float4*)Xs)[(j * 32 + ng) * 17 + kc];
#pragma unroll
            for (int q = 0; q < 4; q++) {
                int kf = stage * 64 + kc * 4 + q;
                const float* wp = &Wsh[fg * 1028 + kf * 8];
                ulonglong2 wa = *(const ulonglong2*)wp;
                ulonglong2 wb = *(const ulonglong2*)(wp + 4);
                float xq[8];
                xq[0] = (q == 0) ? xv[0].x : (q == 1) ? xv[0].y : (q == 2) ? xv[0].z : xv[0].w;
#pragma unroll
                for (int j = 0; j < 8; j++) {
                    float xs = (q == 0) ? xv[j].x : (q == 1) ? xv[j].y
                             : (q == 2) ? xv[j].z : xv[j].w;
                    unsigned long long xd = pack2(xs);
                    acc[j][0] = fma2(xd, wa.x, acc[j][0]);
                    acc[j][1] = fma2(xd, wa.y, acc[j][1]);
                    acc[j][2] = fma2(xd, wb.x, acc[j][2]);
                    acc[j][3] = fma2(xd, wb.y, acc[j][3]);
                }
            }
        }
        __syncthreads();
    }

#pragma unroll
    for (int j = 0; j < 8; j++) {
        int gn = nb + j * 32 + ng;
        if (gn >= NN) continue;
        float2 p0 = unpack2(acc[j][0]), p1 = unpack2(acc[j][1]);
        float2 p2 = unpack2(acc[j][2]), p3 = unpack2(acc[j][3]);
        ((float4*)g_h1)[gn * 16 + fg * 2]     = make_float4(p0.x, p0.y, p1.x, p1.y);
        ((float4*)g_h1)[gn * 16 + fg * 2 + 1] = make_float4(p2.x, p2.y, p3.x, p3.y);
    }
}

// ---------------------------------------------------------------
// Gather layer 1: 16-lane group per node, float4 per lane (row = 16 x float4).
__global__ __launch_bounds__(256) void k_gather1(const float* __restrict__ b1) {
    int tid = blockIdx.x * 256 + threadIdx.x;
    int c = tid >> 4;
    int sub = threadIdx.x & 15;
    if (c >= NN) return;

    const float4* H = (const float4*)g_h1;     // row stride 16
    float di = g_dinv[c];
    float d2 = di * di;
    float4 hc = H[c * 16 + sub];
    float ax = d2 * hc.x, ay = d2 * hc.y, az = d2 * hc.z, aw = d2 * hc.w;

    int i = g_off[c], end = g_off[c + 1];
    for (; i + 3 < end; i += 4) {
        int2 e0 = g_csr[i],     e1 = g_csr[i + 1];
        int2 e2 = g_csr[i + 2], e3 = g_csr[i + 3];
        float4 h0 = H[e0.x * 16 + sub];
        float4 h1 = H[e1.x * 16 + sub];
        float4 h2 = H[e2.x * 16 + sub];
        float4 h3 = H[e3.x * 16 + sub];
        float n0 = __int_as_float(e0.y), n1 = __int_as_float(e1.y);
        float n2 = __int_as_float(e2.y), n3 = __int_as_float(e3.y);
        ax += n0 * h0.x + n1 * h1.x + n2 * h2.x + n3 * h3.x;
        ay += n0 * h0.y + n1 * h1.y + n2 * h2.y + n3 * h3.y;
        az += n0 * h0.z + n1 * h1.z + n2 * h2.z + n3 * h3.z;
        aw += n0 * h0.w + n1 * h1.w + n2 * h2.w + n3 * h3.w;
    }
    for (; i < end; i++) {
        int2 e0 = g_csr[i];
        float4 h0 = H[e0.x * 16 + sub];
        float n0 = __int_as_float(e0.y);
        ax += n0 * h0.x; ay += n0 * h0.y; az += n0 * h0.z; aw += n0 * h0.w;
    }

    float4 bb = ((const float4*)b1)[sub];
    float4 z;
    z.x = fmaxf(ax + bb.x, 0.f);
    z.y = fmaxf(ay + bb.y, 0.f);
    z.z = fmaxf(az + bb.z, 0.f);
    z.w = fmaxf(aw + bb.w, 0.f);
    ((float4*)g_z1)[c * 16 + sub] = z;
}

// ---------------------------------------------------------------
// GEMM2: H2 = z1[NN,64] @ W2[64,32], FFMA2, vectorized X LDS.
// 128 nodes/block; thread = 4 nodes (j*32+ng) x 4 outputs (2 pairs).
__global__ __launch_bounds__(256) void k_gemm2(const float* __restrict__ W2) {
    __shared__ __align__(16) float Xs[128 * 68];  // 128 x (64+4)
    __shared__ __align__(16) float Ws[64 * 32];

    int nb = blockIdx.x * 128;
    int tid = threadIdx.x;

    for (int i = tid; i < 64 * 32 / 4; i += 256)
        ((float4*)Ws)[i] = ((const float4*)W2)[i];

    for (int i = tid; i < 128 * 16; i += 256) {
        int node = i >> 4, k4 = i & 15;
        int gn = nb + node;
        float4 v = make_float4(0.f, 0.f, 0.f, 0.f);
        if (gn < NN) v = ((const float4*)g_z1)[gn * 16 + k4];
        *(float4*)&Xs[node * 68 + k4 * 4] = v;
    }
    __syncthreads();

    int fg = tid & 7;   // f = fg*4 .. fg*4+3 (2 pairs)
    int ng = tid >> 3;  // node: j*32 + ng

    unsigned long long acc[4][2];
#pragma unroll
    for (int j = 0; j < 4; j++) { acc[j][0] = 0ull; acc[j][1] = 0ull; }

#pragma unroll 4
    for (int kc = 0; kc < 16; kc++) {          // 4 k per iter
        float4 xv[4];
#pragma unroll
        for (int j = 0; j < 4; j++)
            xv[j] = ((const float4*)Xs)[(j * 32 + ng) * 17 + kc];
#pragma unroll
        for (int q = 0; q < 4; q++) {
            int k = kc * 4 + q;
            ulonglong2 w = *(const ulonglong2*)&Ws[k * 32 + fg * 4];
#pragma unroll
            for (int j = 0; j < 4; j++) {
                float xs = (q == 0) ? xv[j].x : (q == 1) ? xv[j].y
                         : (q == 2) ? xv[j].z : xv[j].w;
                unsigned long long xd = pack2(xs);
                acc[j][0] = fma2(xd, w.x, acc[j][0]);
                acc[j][1] = fma2(xd, w.y, acc[j][1]);
            }
        }
    }

#pragma unroll
    for (int j = 0; j < 4; j++) {
        int gn = nb + j * 32 + ng;
        if (gn >= NN) continue;
        float2 p0 = unpack2(acc[j][0]), p1 = unpack2(acc[j][1]);
        ((float4*)g_h2)[gn * 8 + fg] = make_float4(p0.x, p0.y, p1.x, p1.y);
    }
}

// ---------------------------------------------------------------
// Gather layer 2: 8-lane group per node, float4 per lane (row = 8 x float4).
__global__ __launch_bounds__(256) void k_gather2(const float* __restrict__ b2,
                                                 float* __restrict__ out) {
    int tid = blockIdx.x * 256 + threadIdx.x;
    int c = tid >> 3;
    int sub = threadIdx.x & 7;
    if (c >= NN) return;

    const float4* H = (const float4*)g_h2;     // row stride 8
    float di = g_dinv[c];
    float d2 = di * di;
    float4 hc = H[c * 8 + sub];
    float ax = d2 * hc.x, ay = d2 * hc.y, az = d2 * hc.z, aw = d2 * hc.w;

    int i = g_off[c], end = g_off[c + 1];
    for (; i + 3 < end; i += 4) {
        int2 e0 = g_csr[i],     e1 = g_csr[i + 1];
        int2 e2 = g_csr[i + 2], e3 = g_csr[i + 3];
        float4 h0 = H[e0.x * 8 + sub];
        float4 h1 = H[e1.x * 8 + sub];
        float4 h2 = H[e2.x * 8 + sub];
        float4 h3 = H[e3.x * 8 + sub];
        float n0 = __int_as_float(e0.y), n1 = __int_as_float(e1.y);
        float n2 = __int_as_float(e2.y), n3 = __int_as_float(e3.y);
        ax += n0 * h0.x + n1 * h1.x + n2 * h2.x + n3 * h3.x;
        ay += n0 * h0.y + n1 * h1.y + n2 * h2.y + n3 * h3.y;
        az += n0 * h0.z + n1 * h1.z + n2 * h2.z + n3 * h3.z;
        aw += n0 * h0.w + n1 * h1.w + n2 * h2.w + n3 * h3.w;
    }
    for (; i < end; i++) {
        int2 e0 = g_csr[i];
        float4 h0 = H[e0.x * 8 + sub];
        float n0 = __int_as_float(e0.y);
        ax += n0 * h0.x; ay += n0 * h0.y; az += n0 * h0.z; aw += n0 * h0.w;
    }

    float4 bb = ((const float4*)b2)[sub];
    ((float4*)out)[c * 8 + sub] =
        make_float4(ax + bb.x, ay + bb.y, az + bb.z, aw + bb.w);
}

// ---------------------------------------------------------------
static const void* by_size(void* const* d_in, const int* in_sizes, int n_in,
                           long long want) {
    for (int i = 0; i < n_in; i++)
        if ((long long)in_sizes[i] == want) return d_in[i];
    return 0;
}

extern "C" void kernel_launch(void* const* d_in, const int* in_sizes, int n_in,
                              void* d_out, int out_size) {
    const float* x  = (const float*)by_size(d_in, in_sizes, n_in, (long long)NN * INF);   // 12.8M
    const void*  ei =               by_size(d_in, in_sizes, n_in, 2LL * NE);              // 3.2M
    const float* ew = (const float*)by_size(d_in, in_sizes, n_in, (long long)NE);         // 1.6M
    const float* W1 = (const float*)by_size(d_in, in_sizes, n_in, (long long)INF * HF);   // 8192
    const float* b1 = (const float*)by_size(d_in, in_sizes, n_in, (long long)HF);         // 64
    const float* W2 = (const float*)by_size(d_in, in_sizes, n_in, (long long)HF * OUTF);  // 2048
    const float* b2 = (const float*)by_size(d_in, in_sizes, n_in, (long long)OUTF);       // 32
    float* out = (float*)d_out;

    cudaFuncSetAttribute(k_gemm1, cudaFuncAttributeMaxDynamicSharedMemorySize, G1_SMEM);

    // Profiled launch is the 4th of this sequence -> k_gemm1 (verify fma-bound).
    k_init   <<<(NN + 255) / 256, 256>>>((const unsigned int*)ei);  // 1
    k_prep1  <<<PREP_G, PREP_B>>>((const int*)ei, ew);              // 2
    k_prep2  <<<PREP_G, PREP_B>>>((const int*)ei, ew);              // 3
    k_gemm1  <<<(NN + 255) / 256, 256, G1_SMEM>>>(x, W1);           // 4 <- profiled
    k_gather1<<<(NN * 16 + 255) / 256, 256>>>(b1);                  // 5
    k_gemm2  <<<(NN + 127) / 128, 256>>>(W2);                       // 6
    k_gather2<<<(NN * 8 + 255) / 256, 256>>>(b2, out);              // 7
}